// round 12
// baseline (speedup 1.0000x reference)
#include <cuda_runtime.h>
#include <cstdint>

#define DD 160
#define NN 82944
#define BB 4
#define WTILE 128           /* columns per tile */
#define G 4                 /* d-groups per column */
#define DG 40               /* rows per group */
#define NTH 512             /* G * WTILE */
#define RS 128              /* tile row stride in floats (512 B) */
#define TILEF (DD * RS)     /* floats per tile buffer (80 KB) */
#define TILE_BYTES (TILEF * 4)
#define PBLKS 144           /* persistent blocks (144 x 18 = 2592 tiles) */
#define TPB 18              /* tiles per block */
#define BLKS_PER_B 36       /* blocks per batch */
#define EPSV 1e-6f
#define NBLKF 81            /* NN / 1024 for float4x256 final kernel */

// Scratch state (device globals: no allocation allowed)
__device__ float g_c[BB * NN];                 // coef
__device__ float g_v[BB * DD];                 // bases vector
__device__ float g_s[BB];                      // ||v||^2
__device__ float g_wp[BB * BLKS_PER_B * DD];   // per-block w partials
__device__ float g_tp[BB * BLKS_PER_B];        // per-block t partials

// ---------------------------------------------------------------------------
// cp.async helpers (LDGSTS on sm_103a)
// ---------------------------------------------------------------------------
__device__ __forceinline__ void cpasync16(uint32_t dst, const void* src) {
    asm volatile("cp.async.cg.shared.global [%0], [%1], 16;\n" :: "r"(dst), "l"(src));
}
__device__ __forceinline__ void cpcommit() {
    asm volatile("cp.async.commit_group;\n" ::: "memory");
}
template <int N>
__device__ __forceinline__ void cpwait() {
    asm volatile("cp.async.wait_group %0;\n" :: "n"(N) : "memory");
}

// ---------------------------------------------------------------------------
// init: v = bases, s = ||v||^2
// ---------------------------------------------------------------------------
__global__ void init_kernel(const float* __restrict__ bases) {
    int b = blockIdx.x, d = threadIdx.x;
    __shared__ float sh[DD];
    float v = bases[b * DD + d];
    g_v[b * DD + d] = v;
    sh[d] = v * v;
    __syncthreads();
    if (d == 0) {
        float s = 0.f;
        for (int i = 0; i < DD; i++) s += sh[i];
        g_s[b] = s;
    }
}

// ---------------------------------------------------------------------------
// One NMF step: double-buffered cp.async prefetch + register-resident passes.
// Thread (g,c) pulls its 40-row column segment from the SMEM tile into regs,
// computes the u-partial, exchanges to form c_new, folds the SAME regs into
// w accumulators. Tile i+2 streams via LDGSTS while tile i computes.
// ---------------------------------------------------------------------------
__global__ void __launch_bounds__(NTH, 1) step_kernel(const float* __restrict__ x,
                                                      int first) {
    __shared__ float v_sh[DD];
    __shared__ float u_sh[NTH];
    __shared__ float c_sh[WTILE];
    __shared__ float wred[16][DG];
    __shared__ float tred[4];
    extern __shared__ float buf[];  // 2 * TILEF floats = 160 KB

    int p = blockIdx.x, tid = threadIdx.x;
    int lane = tid & 31, wrp = tid >> 5;
    int g = tid >> 7;            // d-group 0..3
    int c = tid & 127;           // column within tile
    int b = p / BLKS_PER_B, pb = p % BLKS_PER_B;
    int blk0 = pb * TPB;

    for (int i = tid; i < DD; i += NTH) v_sh[i] = g_v[b * DD + i];
    float s = g_s[b];

    // Copy engine: 10 x 16B chunks per thread per tile.
    // chunk idx = it*512 + tid; row = it*16 + (tid>>5); ch = lane.
    int crow = tid >> 5;                 // base row 0..15
    int ch4 = lane * 4;                  // float offset of 16B chunk
    const float* gbase = x + (size_t)b * DD * NN + (size_t)crow * NN + ch4;
    uint32_t sbase = (uint32_t)__cvta_generic_to_shared(buf);
    uint32_t sthr = sbase + (uint32_t)(crow * RS + ch4) * 4u;

#define ISSUE_TILE(t)                                                        \
    do {                                                                     \
        const float* gsrc = gbase + (size_t)(blk0 + (t)) * WTILE;            \
        uint32_t sdst = sthr + (uint32_t)(((t) & 1) * TILE_BYTES);           \
        _Pragma("unroll")                                                    \
        for (int it = 0; it < 10; it++) {                                    \
            cpasync16(sdst + (uint32_t)(it * 16 * RS) * 4u,                  \
                      gsrc + (size_t)(it * 16) * NN);                        \
        }                                                                    \
        cpcommit();                                                          \
    } while (0)

    const float* vg = v_sh + g * DG;

    float wacc[DG];
#pragma unroll
    for (int k = 0; k < DG; k++) wacc[k] = 0.f;
    float tacc = 0.f;

    ISSUE_TILE(0);
    ISSUE_TILE(1);

    for (int i = 0; i < TPB; i++) {
        if (i + 1 < TPB) cpwait<1>(); else cpwait<0>();
        __syncthreads();  // tile i complete for all threads

        const float* tile = buf + (i & 1) * TILEF + g * DG * RS + c;

        // ---- pull column segment into registers, compute u partial
        float xr[DG];
#pragma unroll
        for (int k = 0; k < DG; k++) xr[k] = tile[k * RS];

        float u0 = 0.f, u1 = 0.f, u2 = 0.f, u3 = 0.f;
#pragma unroll
        for (int k = 0; k < DG; k += 4) {
            u0 = fmaf(xr[k + 0], vg[k + 0], u0);
            u1 = fmaf(xr[k + 1], vg[k + 1], u1);
            u2 = fmaf(xr[k + 2], vg[k + 2], u2);
            u3 = fmaf(xr[k + 3], vg[k + 3], u3);
        }
        u_sh[tid] = (u0 + u1) + (u2 + u3);
        __syncthreads();  // all LDS of this tile done -> slot reusable

        // ---- prefetch tile i+2 into the slot just freed
        if (i + 2 < TPB) ISSUE_TILE(i + 2);

        // ---- combine 4 group-partials, update c (threads 0..127)
        if (tid < WTILE) {
            float u = u_sh[tid] + u_sh[tid + 128] + u_sh[tid + 256] + u_sh[tid + 384];
            size_t cidx = (size_t)b * NN + (size_t)(blk0 + i) * WTILE + tid;
            float cold = first ? 1.f : g_c[cidx];
            float cn = cold * u / (cold * s + EPSV);
            g_c[cidx] = cn;
            c_sh[tid] = cn;
            tacc = fmaf(cn, cn, tacc);
        }
        __syncthreads();

        // ---- fold registers into w accumulators
        float cn = c_sh[c];
#pragma unroll
        for (int k = 0; k < DG; k++) wacc[k] = fmaf(xr[k], cn, wacc[k]);
        // c_sh rewritten only after next iteration's barriers -> safe
    }
#undef ISSUE_TILE

    // ---- end-of-step reductions (once per block)
    if (tid < WTILE) {
#pragma unroll
        for (int off = 16; off; off >>= 1)
            tacc += __shfl_xor_sync(0xffffffffu, tacc, off);
        if (lane == 0) tred[wrp] = tacc;
    }
#pragma unroll
    for (int k = 0; k < DG; k++) {
        float a = wacc[k];
#pragma unroll
        for (int off = 16; off; off >>= 1)
            a += __shfl_xor_sync(0xffffffffu, a, off);
        if (lane == 0) wred[wrp][k] = a;
    }
    __syncthreads();
    if (tid == 0)
        g_tp[b * BLKS_PER_B + pb] = tred[0] + tred[1] + tred[2] + tred[3];
    if (tid < DD) {
        int gg = tid / DG, k = tid % DG;
        g_wp[(size_t)(b * BLKS_PER_B + pb) * DD + tid] =
            wred[4 * gg + 0][k] + wred[4 * gg + 1][k] +
            wred[4 * gg + 2][k] + wred[4 * gg + 3][k];
    }
}

// ---------------------------------------------------------------------------
// v update: sum 36 partials, v = v*w/(v*t+eps), s = ||v||^2
// ---------------------------------------------------------------------------
__global__ void vupdate_kernel() {
    __shared__ float shs[DD];
    __shared__ float tsh;
    int b = blockIdx.x, tid = threadIdx.x;  // 160 threads

    float w = 0.f;
    for (int j = 0; j < BLKS_PER_B; j++)
        w += g_wp[(size_t)(b * BLKS_PER_B + j) * DD + tid];
    if (tid == 0) {
        float t = 0.f;
        for (int j = 0; j < BLKS_PER_B; j++) t += g_tp[b * BLKS_PER_B + j];
        tsh = t;
    }
    __syncthreads();

    float vd = g_v[b * DD + tid];
    float vn = vd * w / (vd * tsh + EPSV);
    g_v[b * DD + tid] = vn;
    shs[tid] = vn * vn;
    __syncthreads();
    if (tid == 0) {
        float s = 0.f;
        for (int i = 0; i < DD; i++) s += shs[i];
        g_s[b] = s;
    }
}

// ---------------------------------------------------------------------------
// Final: u = X^T v, c' = c*u/(c*s+eps), out = v c'^T.
// float4 per thread, 256-thread blocks.
// ---------------------------------------------------------------------------
__global__ void __launch_bounds__(256) final_kernel(const float* __restrict__ x,
                                                    float* __restrict__ out) {
    __shared__ float v_sh[DD];
    int b = blockIdx.y, tid = threadIdx.x;
    size_t n0 = (size_t)blockIdx.x * 1024 + (size_t)tid * 4;

    for (int i = tid; i < DD; i += 256) v_sh[i] = g_v[b * DD + i];
    __syncthreads();
    float s = g_s[b];

    const float* xb = x + (size_t)b * DD * NN + n0;
    float* ob = out + (size_t)b * DD * NN + n0;

    float4 u = make_float4(0.f, 0.f, 0.f, 0.f);
#pragma unroll 8
    for (int d = 0; d < DD; d++) {
        float4 xv = *reinterpret_cast<const float4*>(xb + (size_t)d * NN);
        float vd = v_sh[d];
        u.x = fmaf(xv.x, vd, u.x);
        u.y = fmaf(xv.y, vd, u.y);
        u.z = fmaf(xv.z, vd, u.z);
        u.w = fmaf(xv.w, vd, u.w);
    }

    float4 co = *reinterpret_cast<const float4*>(g_c + (size_t)b * NN + n0);
    float4 cn;
    cn.x = co.x * u.x / (co.x * s + EPSV);
    cn.y = co.y * u.y / (co.y * s + EPSV);
    cn.z = co.z * u.z / (co.z * s + EPSV);
    cn.w = co.w * u.w / (co.w * s + EPSV);

#pragma unroll 8
    for (int d = 0; d < DD; d++) {
        float vd = v_sh[d];
        float4 o = make_float4(vd * cn.x, vd * cn.y, vd * cn.z, vd * cn.w);
        *reinterpret_cast<float4*>(ob + (size_t)d * NN) = o;
    }
}

// ---------------------------------------------------------------------------
extern "C" void kernel_launch(void* const* d_in, const int* in_sizes, int n_in,
                              void* d_out, int out_size) {
    const float* x = (const float*)d_in[0];
    const float* bases = (const float*)d_in[1];
    float* out = (float*)d_out;

    cudaFuncSetAttribute(step_kernel, cudaFuncAttributeMaxDynamicSharedMemorySize,
                         2 * TILE_BYTES);

    init_kernel<<<BB, DD>>>(bases);
    for (int s = 0; s < 4; s++) {
        step_kernel<<<PBLKS, NTH, 2 * TILE_BYTES>>>(x, s == 0);
        vupdate_kernel<<<BB, DD>>>();
    }
    final_kernel<<<dim3(NBLKF, BB), 256>>>(x, out);
}

// round 16
// speedup vs baseline: 1.1885x; 1.1885x over previous
#include <cuda_runtime.h>
#include <cstdint>

#define DD 160
#define NN 82944
#define BB 4
#define WTILE 64            /* columns per tile */
#define G 4                 /* d-groups per column */
#define DG 40               /* rows per group */
#define NTH 256             /* G * WTILE */
#define PBLKS 288           /* persistent blocks (288 x 18 = 5184 tiles) */
#define TPB 18              /* tiles per block */
#define BLKS_PER_B 72       /* blocks per batch */
#define EPSV 1e-6f
#define NBLKF 81            /* NN / 1024 for float4x256 final kernel */

// Scratch state (device globals: no allocation allowed)
__device__ float g_c[BB * NN];                 // coef
__device__ float g_v[BB * DD];                 // bases vector
__device__ float g_s[BB];                      // ||v||^2
__device__ float g_wp[BB * BLKS_PER_B * DD];   // per-block w partials
__device__ float g_tp[BB * BLKS_PER_B];        // per-block t partials

// ---------------------------------------------------------------------------
// init: v = bases, s = ||v||^2
// ---------------------------------------------------------------------------
__global__ void init_kernel(const float* __restrict__ bases) {
    int b = blockIdx.x, d = threadIdx.x;
    __shared__ float sh[DD];
    float v = bases[b * DD + d];
    g_v[b * DD + d] = v;
    sh[d] = v * v;
    __syncthreads();
    if (d == 0) {
        float s = 0.f;
        for (int i = 0; i < DD; i++) s += sh[i];
        g_s[b] = s;
    }
}

// ---------------------------------------------------------------------------
// One NMF step: 2 blocks/SM, register-resident X. Thread (g,c) loads its
// 40-row column segment once (coalesced full-line LDGs), contributes a
// u-partial, exchanges to form c_new, folds the SAME registers into w
// accumulators. The co-resident block's loads fill this block's sync gaps.
// ---------------------------------------------------------------------------
__global__ void __launch_bounds__(NTH, 2) step_kernel(const float* __restrict__ x,
                                                      int first) {
    __shared__ float v_sh[DD];
    __shared__ float u_sh[NTH];
    __shared__ float c_sh[WTILE];
    __shared__ float wred[8][DG];
    __shared__ float tred[2];

    int p = blockIdx.x, tid = threadIdx.x;
    int lane = tid & 31, wrp = tid >> 5;
    int g = tid >> 6;            // d-group 0..3
    int c = tid & 63;            // column within tile
    int b = p / BLKS_PER_B, pb = p % BLKS_PER_B;
    int blk0 = pb * TPB;

    for (int i = tid; i < DD; i += NTH) v_sh[i] = g_v[b * DD + i];
    float s = g_s[b];
    __syncthreads();

    const float* xp0 = x + ((size_t)b * DD + g * DG) * NN
                         + (size_t)blk0 * WTILE + c;
    const float* vg = v_sh + g * DG;

    float wacc[DG];
#pragma unroll
    for (int k = 0; k < DG; k++) wacc[k] = 0.f;
    float tacc = 0.f;

    for (int i = 0; i < TPB; i++) {
        // ---- prefetch old coef early (overlaps with the X loads below)
        size_t cidx = (size_t)b * NN + (size_t)(blk0 + i) * WTILE + c;
        float cold = 1.f;
        if (!first && tid < WTILE) cold = __ldg(&g_c[cidx]);

        const float* xp = xp0 + (size_t)i * WTILE;

        // ---- load 40 rows of this column into registers (batched LDGs)
        float xr[DG];
#pragma unroll
        for (int k = 0; k < DG; k++) xr[k] = xp[(size_t)k * NN];

        // ---- u partial
        float u0 = 0.f, u1 = 0.f, u2 = 0.f, u3 = 0.f;
#pragma unroll
        for (int k = 0; k < DG; k += 4) {
            u0 = fmaf(xr[k + 0], vg[k + 0], u0);
            u1 = fmaf(xr[k + 1], vg[k + 1], u1);
            u2 = fmaf(xr[k + 2], vg[k + 2], u2);
            u3 = fmaf(xr[k + 3], vg[k + 3], u3);
        }
        u_sh[tid] = (u0 + u1) + (u2 + u3);
        __syncthreads();

        // ---- combine 4 group-partials, update c (threads 0..63)
        if (tid < WTILE) {
            float u = u_sh[tid] + u_sh[tid + 64] + u_sh[tid + 128] + u_sh[tid + 192];
            float cn = cold * u / (cold * s + EPSV);
            g_c[cidx] = cn;
            c_sh[tid] = cn;
            tacc = fmaf(cn, cn, tacc);
        }
        __syncthreads();

        // ---- fold registers into w accumulators
        float cn = c_sh[c];
#pragma unroll
        for (int k = 0; k < DG; k++) wacc[k] = fmaf(xr[k], cn, wacc[k]);
        // c_sh rewritten only after next iteration's barriers -> safe
    }

    // ---- end-of-step reductions (once per block)
    if (tid < WTILE) {
#pragma unroll
        for (int off = 16; off; off >>= 1)
            tacc += __shfl_xor_sync(0xffffffffu, tacc, off);
        if (lane == 0) tred[wrp] = tacc;
    }
#pragma unroll
    for (int k = 0; k < DG; k++) {
        float a = wacc[k];
#pragma unroll
        for (int off = 16; off; off >>= 1)
            a += __shfl_xor_sync(0xffffffffu, a, off);
        if (lane == 0) wred[wrp][k] = a;   // warp wrp covers (g = wrp/2)
    }
    __syncthreads();
    if (tid == 0) g_tp[b * BLKS_PER_B + pb] = tred[0] + tred[1];
    if (tid < DD) {
        int gg = tid / DG, k = tid % DG;
        g_wp[(size_t)(b * BLKS_PER_B + pb) * DD + tid] =
            wred[2 * gg][k] + wred[2 * gg + 1][k];
    }
}

// ---------------------------------------------------------------------------
// v update: sum 72 partials, v = v*w/(v*t+eps), s = ||v||^2
// ---------------------------------------------------------------------------
__global__ void vupdate_kernel() {
    __shared__ float shs[DD];
    __shared__ float tsh;
    int b = blockIdx.x, tid = threadIdx.x;  // 160 threads

    float w = 0.f;
    for (int j = 0; j < BLKS_PER_B; j++)
        w += g_wp[(size_t)(b * BLKS_PER_B + j) * DD + tid];
    if (tid == 0) {
        float t = 0.f;
        for (int j = 0; j < BLKS_PER_B; j++) t += g_tp[b * BLKS_PER_B + j];
        tsh = t;
    }
    __syncthreads();

    float vd = g_v[b * DD + tid];
    float vn = vd * w / (vd * tsh + EPSV);
    g_v[b * DD + tid] = vn;
    shs[tid] = vn * vn;
    __syncthreads();
    if (tid == 0) {
        float s = 0.f;
        for (int i = 0; i < DD; i++) s += shs[i];
        g_s[b] = s;
    }
}

// ---------------------------------------------------------------------------
// Final: u = X^T v, c' = c*u/(c*s+eps), out = v c'^T.
// float4 per thread, 256-thread blocks.
// ---------------------------------------------------------------------------
__global__ void __launch_bounds__(256) final_kernel(const float* __restrict__ x,
                                                    float* __restrict__ out) {
    __shared__ float v_sh[DD];
    int b = blockIdx.y, tid = threadIdx.x;
    size_t n0 = (size_t)blockIdx.x * 1024 + (size_t)tid * 4;

    for (int i = tid; i < DD; i += 256) v_sh[i] = g_v[b * DD + i];
    __syncthreads();
    float s = g_s[b];

    const float* xb = x + (size_t)b * DD * NN + n0;
    float* ob = out + (size_t)b * DD * NN + n0;

    float4 u = make_float4(0.f, 0.f, 0.f, 0.f);
#pragma unroll 8
    for (int d = 0; d < DD; d++) {
        float4 xv = *reinterpret_cast<const float4*>(xb + (size_t)d * NN);
        float vd = v_sh[d];
        u.x = fmaf(xv.x, vd, u.x);
        u.y = fmaf(xv.y, vd, u.y);
        u.z = fmaf(xv.z, vd, u.z);
        u.w = fmaf(xv.w, vd, u.w);
    }

    float4 co = *reinterpret_cast<const float4*>(g_c + (size_t)b * NN + n0);
    float4 cn;
    cn.x = co.x * u.x / (co.x * s + EPSV);
    cn.y = co.y * u.y / (co.y * s + EPSV);
    cn.z = co.z * u.z / (co.z * s + EPSV);
    cn.w = co.w * u.w / (co.w * s + EPSV);

#pragma unroll 8
    for (int d = 0; d < DD; d++) {
        float vd = v_sh[d];
        float4 o = make_float4(vd * cn.x, vd * cn.y, vd * cn.z, vd * cn.w);
        *reinterpret_cast<float4*>(ob + (size_t)d * NN) = o;
    }
}

// ---------------------------------------------------------------------------
extern "C" void kernel_launch(void* const* d_in, const int* in_sizes, int n_in,
                              void* d_out, int out_size) {
    const float* x = (const float*)d_in[0];
    const float* bases = (const float*)d_in[1];
    float* out = (float*)d_out;

    init_kernel<<<BB, DD>>>(bases);
    for (int s = 0; s < 4; s++) {
        step_kernel<<<PBLKS, NTH>>>(x, s == 0);
        vupdate_kernel<<<BB, DD>>>();
    }
    final_kernel<<<dim3(NBLKF, BB), 256>>>(x, out);
}